// round 2
// baseline (speedup 1.0000x reference)
#include <cuda_runtime.h>
#include <math.h>

#define D      256
#define SEQ    2046
#define HEADS  8
#define DK     32
#define MHALF  1024
#define NGROUP 64   // B(4) * rate(2) * heads(8)

// group-major qkv scratch: [ (b*2+r)*8+h ][ i (0..1023) ][ d (0..31) ]
__device__ float g_qkv[(size_t)NGROUP * MHALF * DK];

// ---------------------------------------------------------------------------
// Kernel 1: qkv = pad(x) @ W + b, written into group-major layout.
// M = 4*2048 = 8192, N = 256, K = 256. Tiles 64x64x16, 256 threads, 4x4/thread.
// ---------------------------------------------------------------------------
__global__ void __launch_bounds__(256) qkv_gemm_kernel(const float* __restrict__ x,
                                                       const float* __restrict__ W,
                                                       const float* __restrict__ bias) {
    __shared__ float As[16][68];   // [k][row], padded to keep float4 reads aligned
    __shared__ float Bs[16][64];   // [k][col]

    const int tid  = threadIdx.x;
    const int ty   = tid >> 4;     // 0..15
    const int tx   = tid & 15;     // 0..15
    const int row0 = blockIdx.x * 64;
    const int col0 = blockIdx.y * 64;

    float acc[4][4];
#pragma unroll
    for (int i = 0; i < 4; i++)
#pragma unroll
        for (int j = 0; j < 4; j++) acc[i][j] = 0.f;

    // A-load assignment: thread -> (row ar, k-chunk ak)
    const int ar = tid >> 2;             // 0..63
    const int ak = (tid & 3) << 2;       // 0,4,8,12
    const int grow = row0 + ar;
    const int gb = grow >> 11;           // batch
    const int gs = grow & 2047;          // padded seq pos
    const float* xrow = (gs < SEQ) ? (x + ((size_t)gb * SEQ + gs) * D) : nullptr;

    // B-load assignment
    const int bk  = tid >> 4;            // 0..15
    const int bn4 = (tid & 15) << 2;     // 0..60

    for (int k0 = 0; k0 < D; k0 += 16) {
        float4 av = make_float4(0.f, 0.f, 0.f, 0.f);
        if (xrow) av = *(const float4*)(xrow + k0 + ak);
        As[ak + 0][ar] = av.x;
        As[ak + 1][ar] = av.y;
        As[ak + 2][ar] = av.z;
        As[ak + 3][ar] = av.w;

        *(float4*)&Bs[bk][bn4] = *(const float4*)&W[(size_t)(k0 + bk) * D + col0 + bn4];
        __syncthreads();

#pragma unroll
        for (int k = 0; k < 16; k++) {
            float4 a4 = *(const float4*)&As[k][ty << 2];
            float4 b4 = *(const float4*)&Bs[k][tx << 2];
            acc[0][0] += a4.x * b4.x; acc[0][1] += a4.x * b4.y; acc[0][2] += a4.x * b4.z; acc[0][3] += a4.x * b4.w;
            acc[1][0] += a4.y * b4.x; acc[1][1] += a4.y * b4.y; acc[1][2] += a4.y * b4.z; acc[1][3] += a4.y * b4.w;
            acc[2][0] += a4.z * b4.x; acc[2][1] += a4.z * b4.y; acc[2][2] += a4.z * b4.z; acc[2][3] += a4.z * b4.w;
            acc[3][0] += a4.w * b4.x; acc[3][1] += a4.w * b4.y; acc[3][2] += a4.w * b4.z; acc[3][3] += a4.w * b4.w;
        }
        __syncthreads();
    }

    // epilogue: add bias, scatter into group-major layout
#pragma unroll
    for (int i = 0; i < 4; i++) {
        const int grow2 = row0 + (ty << 2) + i;
        const int b = grow2 >> 11;
        const int s = grow2 & 2047;
        const int ii = s >> 1;
        const int r  = s & 1;
#pragma unroll
        for (int j = 0; j < 4; j++) {
            const int c = col0 + (tx << 2) + j;
            const int h = c >> 5;
            const int d = c & 31;
            g_qkv[((size_t)((b * 2 + r) * HEADS + h) * MHALF + ii) * DK + d] = acc[i][j] + bias[c];
        }
    }
}

// ---------------------------------------------------------------------------
// Kernel 2: per-group flash attention.
// Row i logits: { x_i . x_j / sqrt(32), j=0..1023 } ++ { l(i-1), l(i), l(i+1) }
// where the local trio duplicates diag/off-diag entries and out-of-range
// neighbors contribute logit 0 with a zero value vector.
// Output_i = sum_j softmax_weights * x_j  (+ local duplicates).
// One thread per query row, 128 queries per CTA, K tiles staged in smem.
// ---------------------------------------------------------------------------
__global__ void __launch_bounds__(128) attn_kernel(float* __restrict__ out) {
    const int g = blockIdx.y;                 // 0..63
    const int t = threadIdx.x;                // 0..127
    const int i = blockIdx.x * 128 + t;       // query row in group

    const float* Xg = g_qkv + (size_t)g * MHALF * DK;
    const float* qp = Xg + (size_t)i * DK;

    float q[32];
#pragma unroll
    for (int v = 0; v < 8; v++) {
        float4 f = *(const float4*)(qp + 4 * v);
        q[4 * v] = f.x; q[4 * v + 1] = f.y; q[4 * v + 2] = f.z; q[4 * v + 3] = f.w;
    }
    const float scale = 0.17677669529663687f; // 1/sqrt(32)

    // local logits (neighbors i-1, i, i+1 in decimated index; zero pad at edges)
    float l1 = 0.f;
#pragma unroll
    for (int d = 0; d < 32; d++) l1 += q[d] * q[d];
    l1 *= scale;

    float l0 = 0.f, l2 = 0.f;
    if (i > 0) {
        const float* p = qp - DK;
#pragma unroll
        for (int v = 0; v < 8; v++) {
            float4 f = *(const float4*)(p + 4 * v);
            l0 += q[4 * v] * f.x + q[4 * v + 1] * f.y + q[4 * v + 2] * f.z + q[4 * v + 3] * f.w;
        }
        l0 *= scale;
    }
    if (i < MHALF - 1) {
        const float* p = qp + DK;
#pragma unroll
        for (int v = 0; v < 8; v++) {
            float4 f = *(const float4*)(p + 4 * v);
            l2 += q[4 * v] * f.x + q[4 * v + 1] * f.y + q[4 * v + 2] * f.z + q[4 * v + 3] * f.w;
        }
        l2 *= scale;
    }

    float mx = fmaxf(l1, fmaxf(l0, l2));
    const float e0 = __expf(l0 - mx);
    const float e1 = __expf(l1 - mx);
    const float e2 = __expf(l2 - mx);
    float denom = e0 + e1 + e2;

    float acc[32];
#pragma unroll
    for (int d = 0; d < 32; d++) acc[d] = e1 * q[d];
    if (i > 0) {
        const float* p = qp - DK;
#pragma unroll
        for (int v = 0; v < 8; v++) {
            float4 f = *(const float4*)(p + 4 * v);
            acc[4 * v]     += e0 * f.x;
            acc[4 * v + 1] += e0 * f.y;
            acc[4 * v + 2] += e0 * f.z;
            acc[4 * v + 3] += e0 * f.w;
        }
    }
    if (i < MHALF - 1) {
        const float* p = qp + DK;
#pragma unroll
        for (int v = 0; v < 8; v++) {
            float4 f = *(const float4*)(p + 4 * v);
            acc[4 * v]     += e2 * f.x;
            acc[4 * v + 1] += e2 * f.y;
            acc[4 * v + 2] += e2 * f.z;
            acc[4 * v + 3] += e2 * f.w;
        }
    }

    // global pass over all 1024 keys, online softmax
    __shared__ float ks[128 * DK];
    for (int kt = 0; kt < MHALF / 128; kt++) {
        __syncthreads();
        const float4* src = (const float4*)(Xg + (size_t)kt * 128 * DK);
        float4* dst = (float4*)ks;
#pragma unroll
        for (int v = 0; v < 8; v++) dst[t + 128 * v] = src[t + 128 * v];
        __syncthreads();

        for (int j = 0; j < 128; j++) {
            float kr[32];
#pragma unroll
            for (int v = 0; v < 8; v++) {
                float4 f = *(const float4*)&ks[j * DK + 4 * v];
                kr[4 * v] = f.x; kr[4 * v + 1] = f.y; kr[4 * v + 2] = f.z; kr[4 * v + 3] = f.w;
            }
            float s = 0.f;
#pragma unroll
            for (int d = 0; d < 32; d++) s += q[d] * kr[d];
            s *= scale;

            if (s > mx) {
                const float fct = __expf(mx - s);
                denom *= fct;
#pragma unroll
                for (int d = 0; d < 32; d++) acc[d] *= fct;
                mx = s;
            }
            const float w = __expf(s - mx);
            denom += w;
#pragma unroll
            for (int d = 0; d < 32; d++) acc[d] += w * kr[d];
        }
    }

    // write back (skip the padded bias rows s >= 2046)
    const int h = g & 7;
    const int r = (g >> 3) & 1;
    const int b = g >> 4;
    const int s = 2 * i + r;
    if (s < SEQ) {
        const float inv = 1.f / denom;
        float* op = out + ((size_t)b * SEQ + s) * D + h * DK;
#pragma unroll
        for (int v = 0; v < 8; v++) {
            float4 f;
            f.x = acc[4 * v]     * inv;
            f.y = acc[4 * v + 1] * inv;
            f.z = acc[4 * v + 2] * inv;
            f.w = acc[4 * v + 3] * inv;
            *(float4*)(op + 4 * v) = f;
        }
    }
}

extern "C" void kernel_launch(void* const* d_in, const int* in_sizes, int n_in,
                              void* d_out, int out_size) {
    const float* x = (const float*)d_in[0];
    const float* W = (const float*)d_in[1];
    const float* b = (const float*)d_in[2];
    float* out = (float*)d_out;

    dim3 gemm_grid(8192 / 64, D / 64);   // 128 x 4
    qkv_gemm_kernel<<<gemm_grid, 256>>>(x, W, b);

    dim3 attn_grid(MHALF / 128, NGROUP); // 8 x 64
    attn_kernel<<<attn_grid, 128>>>(out);
}